// round 1
// baseline (speedup 1.0000x reference)
#include <cuda_runtime.h>
#include <math.h>

#define Bb 256
#define Nn 30
#define Ll 49
#define Vv 2000
#define WDc 300
#define Dd 256
#define NBc 64
#define Rr 50

// Output layout (concatenated flattened outputs in reference return order)
#define O_IMG 0
#define O_TGT (Bb*NBc)                  // 16384
#define O_WV  (2*Bb*NBc)                // 32768
#define O_SV  (O_WV + Bb*Nn*WDc)        // 2336768
#define O_ST  (O_SV + Bb*Ll)            // 2349312
#define O_SV2 (O_ST + Bb*Nn)            // 2356992
#define O_KG  (O_SV2 + Bb*Ll)           // 2369536

// Scratch: M = Wht @ Wc  (NB x WD), bb[k] = bht[k] + bc . Wht[k]
__device__ float g_M[NBc*WDc];
__device__ float g_bb[NBc];

// ---------------------------------------------------------------------------
// Kernel P: precompute M and bb.  8 blocks x 256 threads, block handles 8 k's.
// ---------------------------------------------------------------------------
__global__ void precompute_M(const float* __restrict__ Wc,
                             const float* __restrict__ Wht,
                             const float* __restrict__ bc,
                             const float* __restrict__ bht) {
    __shared__ float s_wht[8][Dd];
    __shared__ float s_bc[Dd];
    int tid = threadIdx.x;
    int k0 = blockIdx.x * 8;
    for (int i = tid; i < 8 * Dd; i += 256)
        s_wht[i >> 8][i & 255] = Wht[(k0 + (i >> 8)) * Dd + (i & 255)];
    s_bc[tid] = bc[tid];
    __syncthreads();

    for (int w = tid; w < WDc; w += 256) {
        float acc[8];
#pragma unroll
        for (int kk = 0; kk < 8; kk++) acc[kk] = 0.f;
        for (int c = 0; c < Dd; c++) {
            float wc = Wc[c * WDc + w];
#pragma unroll
            for (int kk = 0; kk < 8; kk++) acc[kk] += s_wht[kk][c] * wc;
        }
#pragma unroll
        for (int kk = 0; kk < 8; kk++) g_M[(k0 + kk) * WDc + w] = acc[kk];
    }
    if (tid < 8) {
        int k = k0 + tid;
        float a = bht[k];
        for (int c = 0; c < Dd; c++) a += s_bc[c] * s_wht[tid][c];
        g_bb[k] = a;
    }
}

// ---------------------------------------------------------------------------
// Kernel B: gather w_vector = word_vectors[targets]  (float4 copies)
// 576000 float4 total, grid 2250 x 256 exactly.
// ---------------------------------------------------------------------------
__global__ void gather_wv(const float4* __restrict__ wv,
                          const int* __restrict__ targets,
                          float4* __restrict__ out) {
    int idx = blockIdx.x * blockDim.x + threadIdx.x;   // < 576000
    int row = idx / 75;
    int q = idx - row * 75;
    int t = __ldg(&targets[row]);
    out[idx] = wv[(size_t)t * 75 + q];
}

// ---------------------------------------------------------------------------
// Kernel A: KG gather + pair mask.  One block per (b, i) pair row.
// ---------------------------------------------------------------------------
__global__ void kg_kernel(const float* __restrict__ rel,
                          const int* __restrict__ targets,
                          const int* __restrict__ lengths,
                          float2* __restrict__ out) {
    int bi = blockIdx.x;              // b*N + i
    int b = bi / Nn;
    int i = bi - b * Nn;
    __shared__ int s_tj[Nn];
    __shared__ int s_len;
    if (threadIdx.x < Nn) s_tj[threadIdx.x] = targets[b * Nn + threadIdx.x] - 4;
    if (threadIdx.x == 0) s_len = lengths[b];
    __syncthreads();
    int len = s_len;
    bool vi = i < len;
    long long tibase = (long long)s_tj[i] * Vv;
    const float2* rel2 = (const float2*)rel;
    float2* o = out + (long long)bi * (Nn * Rr / 2);
    const int TOT = Nn * Rr / 2;  // 750 float2
    for (int e = threadIdx.x; e < TOT; e += blockDim.x) {
        int j = e / 25;
        int r2 = e - j * 25;
        float2 v = make_float2(0.f, 0.f);
        if (vi && j < len) v = rel2[(tibase + s_tj[j]) * 25 + r2];
        o[e] = v;
    }
}

// ---------------------------------------------------------------------------
// Kernel C: fused per-batch kernel. One block per b, 256 threads.
// ---------------------------------------------------------------------------
#define HS_S 260
#define LG_S 33

struct __align__(16) SmemC {
    float hs[Nn][HS_S];
    float iff[Ll][HS_S];
    float logits[Ll][LG_S];
    float w1[Dd], w2[Dd];
    float hsW1[Nn], tl[Nn], st[Nn];
    float v2l[Ll], svl[Ll], sv[Ll];
    float svwv[WDc];
    float oiv[Dd];
    int tgt[Nn];
};

__device__ __forceinline__ void warp_softmax(const float* src, float* dst_s,
                                             float* dst_g, int cnt, int lane) {
    float v0 = lane < cnt ? src[lane] : -1e30f;
    float v1 = (lane + 32) < cnt ? src[lane + 32] : -1e30f;
    float m = fmaxf(v0, v1);
    for (int o = 16; o; o >>= 1) m = fmaxf(m, __shfl_xor_sync(0xffffffffu, m, o));
    float e0 = lane < cnt ? expf(v0 - m) : 0.f;
    float e1 = (lane + 32) < cnt ? expf(v1 - m) : 0.f;
    float s = e0 + e1;
    for (int o = 16; o; o >>= 1) s += __shfl_xor_sync(0xffffffffu, s, o);
    float inv = 1.f / s;
    if (lane < cnt) {
        float r = e0 * inv;
        if (dst_s) dst_s[lane] = r;
        dst_g[lane] = r;
    }
    if (lane + 32 < cnt) {
        float r = e1 * inv;
        if (dst_s) dst_s[lane + 32] = r;
        dst_g[lane + 32] = r;
    }
}

__global__ __launch_bounds__(256, 2) void batch_kernel(
    const float* __restrict__ img_feat, const float* __restrict__ hs_g,
    const float* __restrict__ tat, const float* __restrict__ wvec,
    const float* __restrict__ W1, const float* __restrict__ W2,
    const float* __restrict__ Whi, const float* __restrict__ bhi,
    const int* __restrict__ targets, float* __restrict__ out) {
    extern __shared__ char smem_raw[];
    SmemC& s = *(SmemC*)smem_raw;
    int b = blockIdx.x, tid = threadIdx.x;
    int lane = tid & 31, wid = tid >> 5;

    // ---- load phase ----
    const float4* hs4 = (const float4*)(hs_g + (size_t)b * Nn * Dd);
    for (int i = tid; i < Nn * 64; i += 256) {
        int n = i >> 6, c4 = i & 63;
        *(float4*)&s.hs[n][c4 * 4] = hs4[n * 64 + c4];
    }
    const float4* if4 = (const float4*)(img_feat + (size_t)b * Ll * Dd);
    for (int i = tid; i < Ll * 64; i += 256) {
        int l = i >> 6, c4 = i & 63;
        *(float4*)&s.iff[l][c4 * 4] = if4[l * 64 + c4];
    }
    if (tid < Dd) { s.w1[tid] = W1[tid]; s.w2[tid] = W2[tid]; }
    if (tid < Nn) s.tgt[tid] = targets[b * Nn + tid];
    __syncthreads();

    // ---- Phase A: per-row dots (hsW1, tanh-logits, s_v2 logits) ----
    const float* tat_b = tat + (size_t)b * Nn * Dd;
    for (int t = wid; t < Nn + Ll; t += 8) {
        if (t < Nn) {
            int n = t;
            float a1 = 0.f, a2 = 0.f;
            for (int c = lane; c < Dd; c += 32) {
                float h = s.hs[n][c];
                a1 += h * s.w1[c];
                a2 += tanhf(tat_b[n * Dd + c] + h) * s.w2[c];
            }
            for (int o = 16; o; o >>= 1) {
                a1 += __shfl_xor_sync(0xffffffffu, a1, o);
                a2 += __shfl_xor_sync(0xffffffffu, a2, o);
            }
            if (lane == 0) { s.hsW1[n] = a1; s.tl[n] = a2; }
        } else {
            int l = t - Nn;
            float a = 0.f;
            for (int c = lane; c < Dd; c += 32) a += s.iff[l][c] * s.w1[c];
            for (int o = 16; o; o >>= 1) a += __shfl_xor_sync(0xffffffffu, a, o);
            if (lane == 0) s.v2l[l] = a;
        }
    }

    // ---- Phase B: logits[l][n] = (img_feat[l] . hs[n]) * scale ----
    // 2 l's x 6 n's per thread; 125 active threads.
    if (tid < 125) {
        int lg = tid / 5, g = tid - lg * 5;
        int l0 = lg * 2, l1 = l0 + 1;
        bool has1 = (l1 < Ll);
        float acc0[6], acc1[6];
#pragma unroll
        for (int kk = 0; kk < 6; kk++) { acc0[kk] = 0.f; acc1[kk] = 0.f; }
        for (int c4 = 0; c4 < 64; c4++) {
            float4 a0 = *(const float4*)&s.iff[l0][c4 * 4];
            float4 a1 = has1 ? *(const float4*)&s.iff[l1][c4 * 4]
                             : make_float4(0.f, 0.f, 0.f, 0.f);
#pragma unroll
            for (int kk = 0; kk < 6; kk++) {
                float4 h = *(const float4*)&s.hs[g * 6 + kk][c4 * 4];
                acc0[kk] += a0.x * h.x + a0.y * h.y + a0.z * h.z + a0.w * h.w;
                acc1[kk] += a1.x * h.x + a1.y * h.y + a1.z * h.z + a1.w * h.w;
            }
        }
        const float scale = 0.0625f;   // 1/sqrt(256)
#pragma unroll
        for (int kk = 0; kk < 6; kk++) {
            s.logits[l0][g * 6 + kk] = acc0[kk] * scale;
            if (has1) s.logits[l1][g * 6 + kk] = acc1[kk] * scale;
        }
    }
    __syncthreads();

    // ---- Phase C: per-l softmax over n fused with s_v logit ----
    if (tid < Ll) {
        int l = tid;
        float m = -1e30f;
        for (int n = 0; n < Nn; n++) m = fmaxf(m, s.logits[l][n]);
        float sum = 0.f, acc = 0.f;
        for (int n = 0; n < Nn; n++) {
            float e = expf(s.logits[l][n] - m);
            sum += e;
            acc += e * s.hsW1[n];
        }
        s.svl[l] = acc / sum;
    }
    __syncthreads();

    // ---- Phase D: the three softmaxes ----
    if (wid == 0) warp_softmax(s.svl, s.sv, out + O_SV + b * Ll, Ll, lane);
    if (wid == 1) warp_softmax(s.v2l, 0, out + O_SV2 + b * Ll, Ll, lane);
    if (wid == 2) warp_softmax(s.tl, s.st, out + O_ST + b * Nn, Nn, lane);
    __syncthreads();

    // ---- Phase E: out_img_vec and s_t-weighted word vectors ----
    {
        int c = tid;
        float a = 0.f;
        for (int l = 0; l < Ll; l++) a += s.sv[l] * s.iff[l][c];
        s.oiv[c] = a;
    }
    for (int w = tid; w < WDc; w += 256) {
        float a = 0.f;
#pragma unroll
        for (int n = 0; n < Nn; n++)
            a += s.st[n] * __ldg(&wvec[(size_t)s.tgt[n] * WDc + w]);
        s.svwv[w] = a;
    }
    __syncthreads();

    // ---- Phase F: final sigmoid heads (warp-dot per k) ----
    for (int k = wid; k < NBc; k += 8) {
        float a = 0.f;
        for (int w = lane; w < WDc; w += 32) a += s.svwv[w] * g_M[k * WDc + w];
        for (int o = 16; o; o >>= 1) a += __shfl_xor_sync(0xffffffffu, a, o);
        if (lane == 0)
            out[O_TGT + b * NBc + k] = 1.f / (1.f + expf(-(a + g_bb[k])));

        float a2 = 0.f;
        for (int c = lane; c < Dd; c += 32) a2 += s.oiv[c] * Whi[k * Dd + c];
        for (int o = 16; o; o >>= 1) a2 += __shfl_xor_sync(0xffffffffu, a2, o);
        if (lane == 0)
            out[O_IMG + b * NBc + k] = 1.f / (1.f + expf(-(a2 + bhi[k])));
    }
}

// ---------------------------------------------------------------------------
extern "C" void kernel_launch(void* const* d_in, const int* in_sizes, int n_in,
                              void* d_out, int out_size) {
    const float* rel     = (const float*)d_in[0];
    const float* wv      = (const float*)d_in[1];
    const float* img     = (const float*)d_in[2];
    const float* hs      = (const float*)d_in[3];
    const float* tat     = (const float*)d_in[4];
    const float* Wc      = (const float*)d_in[5];
    const float* bc      = (const float*)d_in[6];
    const float* W1      = (const float*)d_in[7];
    const float* W2      = (const float*)d_in[8];
    const float* Whi     = (const float*)d_in[9];
    const float* bhi     = (const float*)d_in[10];
    const float* Wht     = (const float*)d_in[11];
    const float* bht     = (const float*)d_in[12];
    const int*   targets = (const int*)d_in[13];
    const int*   lengths = (const int*)d_in[14];
    float* out = (float*)d_out;

    cudaFuncSetAttribute(batch_kernel,
                         cudaFuncAttributeMaxDynamicSharedMemorySize,
                         (int)sizeof(SmemC));

    precompute_M<<<8, 256>>>(Wc, Wht, bc, bht);
    gather_wv<<<2250, 256>>>((const float4*)wv, targets,
                             (float4*)(out + O_WV));
    batch_kernel<<<Bb, 256, sizeof(SmemC)>>>(img, hs, tat, wv, W1, W2, Whi,
                                             bhi, targets, out);
    kg_kernel<<<Bb * Nn, 256>>>(rel, targets, lengths,
                                (float2*)(out + O_KG));
}

// round 2
// speedup vs baseline: 1.6289x; 1.6289x over previous
#include <cuda_runtime.h>
#include <math.h>

#define Bb 256
#define Nn 30
#define Ll 49
#define Vv 2000
#define WDc 300
#define Dd 256
#define NBc 64
#define Rr 50

// Output layout (concatenated flattened outputs in reference return order)
#define O_IMG 0
#define O_TGT (Bb*NBc)                  // 16384
#define O_WV  (2*Bb*NBc)                // 32768
#define O_SV  (O_WV + Bb*Nn*WDc)        // 2336768
#define O_ST  (O_SV + Bb*Ll)            // 2349312
#define O_SV2 (O_ST + Bb*Nn)            // 2356992
#define O_KG  (O_SV2 + Bb*Ll)           // 2369536

// Scratch: M = Wht @ Wc  (NB x WD), bb[k] = bht[k] + bc . Wht[k]
__device__ float g_M[NBc*WDc];
__device__ float g_bb[NBc];

// ---------------------------------------------------------------------------
// Kernel P: precompute M and bb.  64 blocks (one k each) x 256 threads.
// ---------------------------------------------------------------------------
__global__ void precompute_M(const float* __restrict__ Wc,
                             const float* __restrict__ Wht,
                             const float* __restrict__ bc,
                             const float* __restrict__ bht) {
    __shared__ float s_wht[Dd];
    int k = blockIdx.x, tid = threadIdx.x;
    s_wht[tid] = Wht[k * Dd + tid];
    __syncthreads();
    float acc0 = 0.f, acc1 = 0.f;
    bool has1 = (tid + 256) < WDc;   // tid < 44
#pragma unroll 8
    for (int c = 0; c < Dd; c++) {
        float wh = s_wht[c];
        acc0 += wh * Wc[c * WDc + tid];
        if (has1) acc1 += wh * Wc[c * WDc + tid + 256];
    }
    g_M[k * WDc + tid] = acc0;
    if (has1) g_M[k * WDc + tid + 256] = acc1;
    if (tid < 32) {
        float a = 0.f;
        for (int c = tid; c < Dd; c += 32) a += s_wht[c] * bc[c];
        for (int o = 16; o; o >>= 1) a += __shfl_xor_sync(0xffffffffu, a, o);
        if (tid == 0) g_bb[k] = a + bht[k];
    }
}

// ---------------------------------------------------------------------------
// Kernel B: gather w_vector = word_vectors[targets]  (float4 copies)
// ---------------------------------------------------------------------------
__global__ void gather_wv(const float4* __restrict__ wv,
                          const int* __restrict__ targets,
                          float4* __restrict__ out) {
    int idx = blockIdx.x * blockDim.x + threadIdx.x;   // < 576000
    int row = idx / 75;
    int q = idx - row * 75;
    int t = __ldg(&targets[row]);
    out[idx] = wv[(size_t)t * 75 + q];
}

// ---------------------------------------------------------------------------
// Kernel A: KG gather + pair mask. One block per b; each thread owns a fixed
// (j, r2) pair (computed once) and loops over i with unrolled MLP.
// ---------------------------------------------------------------------------
__global__ __launch_bounds__(768) void kg_kernel(
    const float* __restrict__ rel, const int* __restrict__ targets,
    const int* __restrict__ lengths, float2* __restrict__ out) {
    int b = blockIdx.x, tid = threadIdx.x;
    __shared__ int s_tj[Nn];
    __shared__ int s_len;
    if (tid < Nn) s_tj[tid] = targets[b * Nn + tid] - 4;
    if (tid == 0) s_len = lengths[b];
    __syncthreads();
    if (tid >= 750) return;
    int j = tid / 25;
    int r2 = tid - j * 25;
    int len = s_len;
    int tj = s_tj[j];
    bool vj = j < len;
    const float2* rel2 = (const float2*)rel;
    float2* o = out + (size_t)b * (Nn * 750) + tid;
#pragma unroll 6
    for (int i = 0; i < Nn; i++) {
        float2 v = make_float2(0.f, 0.f);
        if (vj && i < len)
            v = rel2[((long long)s_tj[i] * Vv + tj) * 25 + r2];
        o[i * 750] = v;
    }
}

// ---------------------------------------------------------------------------
// Kernel C: fused per-batch kernel. One block per b, 256 threads.
// Warps 0-3: logits microkernel (Phase B). Warps 4-7: row dots (Phase A).
// ---------------------------------------------------------------------------
#define HS_S 260
#define LG_S 33

struct __align__(16) SmemC {
    float hs[Nn][HS_S];
    float iff[Ll][HS_S];
    float logits[Ll][LG_S];
    float w1[Dd], w2[Dd];
    float hsW1[Nn], tl[Nn], st[Nn];
    float v2l[Ll], svl[Ll], sv[Ll];
    float svwv[WDc];
    float oiv[Dd];
    int tgt[Nn];
};

__device__ __forceinline__ void warp_softmax(const float* src, float* dst_s,
                                             float* dst_g, int cnt, int lane) {
    float v0 = lane < cnt ? src[lane] : -1e30f;
    float v1 = (lane + 32) < cnt ? src[lane + 32] : -1e30f;
    float m = fmaxf(v0, v1);
    for (int o = 16; o; o >>= 1) m = fmaxf(m, __shfl_xor_sync(0xffffffffu, m, o));
    float e0 = lane < cnt ? expf(v0 - m) : 0.f;
    float e1 = (lane + 32) < cnt ? expf(v1 - m) : 0.f;
    float s = e0 + e1;
    for (int o = 16; o; o >>= 1) s += __shfl_xor_sync(0xffffffffu, s, o);
    float inv = 1.f / s;
    if (lane < cnt) {
        float r = e0 * inv;
        if (dst_s) dst_s[lane] = r;
        dst_g[lane] = r;
    }
    if (lane + 32 < cnt) {
        float r = e1 * inv;
        if (dst_s) dst_s[lane + 32] = r;
        dst_g[lane + 32] = r;
    }
}

__global__ __launch_bounds__(256, 2) void batch_kernel(
    const float* __restrict__ img_feat, const float* __restrict__ hs_g,
    const float* __restrict__ tat, const float* __restrict__ wvec,
    const float* __restrict__ W1, const float* __restrict__ W2,
    const float* __restrict__ Whi, const float* __restrict__ bhi,
    const int* __restrict__ targets, float* __restrict__ out) {
    extern __shared__ char smem_raw[];
    SmemC& s = *(SmemC*)smem_raw;
    int b = blockIdx.x, tid = threadIdx.x;
    int lane = tid & 31, wid = tid >> 5;

    // ---- load phase ----
    const float4* hs4 = (const float4*)(hs_g + (size_t)b * Nn * Dd);
    for (int i = tid; i < Nn * 64; i += 256) {
        int n = i >> 6, c4 = i & 63;
        *(float4*)&s.hs[n][c4 * 4] = hs4[n * 64 + c4];
    }
    const float4* if4 = (const float4*)(img_feat + (size_t)b * Ll * Dd);
    for (int i = tid; i < Ll * 64; i += 256) {
        int l = i >> 6, c4 = i & 63;
        *(float4*)&s.iff[l][c4 * 4] = if4[l * 64 + c4];
    }
    if (tid < Dd) { s.w1[tid] = W1[tid]; s.w2[tid] = W2[tid]; }
    if (tid < Nn) s.tgt[tid] = targets[b * Nn + tid];
    __syncthreads();

    if (wid >= 4) {
        // ---- Phase A: per-row dots (hsW1, tanh-logits, s_v2 logits) ----
        const float* tat_b = tat + (size_t)b * Nn * Dd;
        for (int t = wid - 4; t < Nn + Ll; t += 4) {
            if (t < Nn) {
                int n = t;
                float a1 = 0.f, a2 = 0.f;
                for (int c = lane; c < Dd; c += 32) {
                    float h = s.hs[n][c];
                    a1 += h * s.w1[c];
                    a2 += tanhf(tat_b[n * Dd + c] + h) * s.w2[c];
                }
                for (int o = 16; o; o >>= 1) {
                    a1 += __shfl_xor_sync(0xffffffffu, a1, o);
                    a2 += __shfl_xor_sync(0xffffffffu, a2, o);
                }
                if (lane == 0) { s.hsW1[n] = a1; s.tl[n] = a2; }
            } else {
                int l = t - Nn;
                float a = 0.f;
                for (int c = lane; c < Dd; c += 32) a += s.iff[l][c] * s.w1[c];
                for (int o = 16; o; o >>= 1) a += __shfl_xor_sync(0xffffffffu, a, o);
                if (lane == 0) s.v2l[l] = a;
            }
        }
    } else if (tid < 125) {
        // ---- Phase B: logits[l][n] = (img_feat[l] . hs[n]) * scale ----
        int lg = tid / 5, g = tid - lg * 5;
        int l0 = lg * 2, l1 = l0 + 1;
        bool has1 = (l1 < Ll);
        float acc0[6], acc1[6];
#pragma unroll
        for (int kk = 0; kk < 6; kk++) { acc0[kk] = 0.f; acc1[kk] = 0.f; }
        for (int c4 = 0; c4 < 64; c4++) {
            float4 a0 = *(const float4*)&s.iff[l0][c4 * 4];
            float4 a1 = has1 ? *(const float4*)&s.iff[l1][c4 * 4]
                             : make_float4(0.f, 0.f, 0.f, 0.f);
#pragma unroll
            for (int kk = 0; kk < 6; kk++) {
                float4 h = *(const float4*)&s.hs[g * 6 + kk][c4 * 4];
                acc0[kk] += a0.x * h.x + a0.y * h.y + a0.z * h.z + a0.w * h.w;
                acc1[kk] += a1.x * h.x + a1.y * h.y + a1.z * h.z + a1.w * h.w;
            }
        }
        const float scale = 0.0625f;   // 1/sqrt(256)
#pragma unroll
        for (int kk = 0; kk < 6; kk++) {
            s.logits[l0][g * 6 + kk] = acc0[kk] * scale;
            if (has1) s.logits[l1][g * 6 + kk] = acc1[kk] * scale;
        }
    }
    __syncthreads();

    // ---- Phase C: per-l softmax over n fused with s_v logit ----
    if (tid < Ll) {
        int l = tid;
        float m = -1e30f;
        for (int n = 0; n < Nn; n++) m = fmaxf(m, s.logits[l][n]);
        float sum = 0.f, acc = 0.f;
        for (int n = 0; n < Nn; n++) {
            float e = expf(s.logits[l][n] - m);
            sum += e;
            acc += e * s.hsW1[n];
        }
        s.svl[l] = acc / sum;
    }
    __syncthreads();

    // ---- Phase D: the three softmaxes ----
    if (wid == 0) warp_softmax(s.svl, s.sv, out + O_SV + b * Ll, Ll, lane);
    if (wid == 1) warp_softmax(s.v2l, 0, out + O_SV2 + b * Ll, Ll, lane);
    if (wid == 2) warp_softmax(s.tl, s.st, out + O_ST + b * Nn, Nn, lane);
    __syncthreads();

    // ---- Phase E: out_img_vec and s_t-weighted word vectors ----
    {
        int c = tid;
        float a = 0.f;
        for (int l = 0; l < Ll; l++) a += s.sv[l] * s.iff[l][c];
        s.oiv[c] = a;
    }
    for (int w = tid; w < WDc; w += 256) {
        float a = 0.f;
#pragma unroll
        for (int n = 0; n < Nn; n++)
            a += s.st[n] * __ldg(&wvec[(size_t)s.tgt[n] * WDc + w]);
        s.svwv[w] = a;
    }
    __syncthreads();

    // ---- Phase F: final sigmoid heads (warp-dot per k) ----
    for (int k = wid; k < NBc; k += 8) {
        float a = 0.f;
        for (int w = lane; w < WDc; w += 32) a += s.svwv[w] * g_M[k * WDc + w];
        for (int o = 16; o; o >>= 1) a += __shfl_xor_sync(0xffffffffu, a, o);
        if (lane == 0)
            out[O_TGT + b * NBc + k] = 1.f / (1.f + expf(-(a + g_bb[k])));

        float a2 = 0.f;
        for (int c = lane; c < Dd; c += 32) a2 += s.oiv[c] * Whi[k * Dd + c];
        for (int o = 16; o; o >>= 1) a2 += __shfl_xor_sync(0xffffffffu, a2, o);
        if (lane == 0)
            out[O_IMG + b * NBc + k] = 1.f / (1.f + expf(-(a2 + bhi[k])));
    }
}

// ---------------------------------------------------------------------------
extern "C" void kernel_launch(void* const* d_in, const int* in_sizes, int n_in,
                              void* d_out, int out_size) {
    const float* rel     = (const float*)d_in[0];
    const float* wv      = (const float*)d_in[1];
    const float* img     = (const float*)d_in[2];
    const float* hs      = (const float*)d_in[3];
    const float* tat     = (const float*)d_in[4];
    const float* Wc      = (const float*)d_in[5];
    const float* bc      = (const float*)d_in[6];
    const float* W1      = (const float*)d_in[7];
    const float* W2      = (const float*)d_in[8];
    const float* Whi     = (const float*)d_in[9];
    const float* bhi     = (const float*)d_in[10];
    const float* Wht     = (const float*)d_in[11];
    const float* bht     = (const float*)d_in[12];
    const int*   targets = (const int*)d_in[13];
    const int*   lengths = (const int*)d_in[14];
    float* out = (float*)d_out;

    cudaFuncSetAttribute(batch_kernel,
                         cudaFuncAttributeMaxDynamicSharedMemorySize,
                         (int)sizeof(SmemC));

    // Fork two side streams off the main (possibly capturing) stream so the
    // independent kernels become parallel graph branches.
    cudaStream_t sA = 0, sB = 0;
    cudaEvent_t eFork = 0, eA = 0, eB = 0;
    bool par = true;
    par &= (cudaStreamCreateWithFlags(&sA, cudaStreamNonBlocking) == cudaSuccess);
    par &= (cudaStreamCreateWithFlags(&sB, cudaStreamNonBlocking) == cudaSuccess);
    par &= (cudaEventCreateWithFlags(&eFork, cudaEventDisableTiming) == cudaSuccess);
    par &= (cudaEventCreateWithFlags(&eA, cudaEventDisableTiming) == cudaSuccess);
    par &= (cudaEventCreateWithFlags(&eB, cudaEventDisableTiming) == cudaSuccess);

    if (par) {
        cudaEventRecord(eFork, 0);
        cudaStreamWaitEvent(sA, eFork, 0);
        cudaStreamWaitEvent(sB, eFork, 0);

        // Branch main: precompute -> batch (dependency via g_M/g_bb)
        precompute_M<<<NBc, 256, 0, 0>>>(Wc, Wht, bc, bht);
        batch_kernel<<<Bb, 256, sizeof(SmemC), 0>>>(img, hs, tat, wv, W1, W2,
                                                    Whi, bhi, targets, out);
        // Branch A: word-vector gather
        gather_wv<<<2250, 256, 0, sA>>>((const float4*)wv, targets,
                                        (float4*)(out + O_WV));
        // Branch B: KG gather
        kg_kernel<<<Bb, 768, 0, sB>>>(rel, targets, lengths,
                                      (float2*)(out + O_KG));

        cudaEventRecord(eA, sA);
        cudaEventRecord(eB, sB);
        cudaStreamWaitEvent(0, eA, 0);
        cudaStreamWaitEvent(0, eB, 0);
    } else {
        precompute_M<<<NBc, 256>>>(Wc, Wht, bc, bht);
        gather_wv<<<2250, 256>>>((const float4*)wv, targets,
                                 (float4*)(out + O_WV));
        batch_kernel<<<Bb, 256, sizeof(SmemC)>>>(img, hs, tat, wv, W1, W2,
                                                 Whi, bhi, targets, out);
        kg_kernel<<<Bb, 768>>>(rel, targets, lengths, (float2*)(out + O_KG));
    }

    if (eA) cudaEventDestroy(eA);
    if (eB) cudaEventDestroy(eB);
    if (eFork) cudaEventDestroy(eFork);
    if (sA) cudaStreamDestroy(sA);
    if (sB) cudaStreamDestroy(sB);
}